// round 6
// baseline (speedup 1.0000x reference)
#include <cuda_runtime.h>
#include <cstdint>

#define NN 8192
#define D 64
#define DO 128
#define K 16
#define SEG 8
#define JSEG (NN/SEG)       // 1024
#define TI 128
#define TJ 64
#define NTILES (JSEG/TJ)    // 16

typedef unsigned long long u64;

// Scratch (no allocs allowed)
__device__ float g_sq[NN];
__device__ float g_p[NN * DO];
__device__ float g_q[NN * DO];
__device__ u64 g_ck[NN * SEG * K];

// Packed fp32x2 FMA (Blackwell FFMA2 — PTX-only path; validated in R2)
__device__ __forceinline__ u64 ffma2(u64 a, u64 b, u64 c) {
    u64 d;
    asm("fma.rn.f32x2 %0, %1, %2, %3;" : "=l"(d) : "l"(a), "l"(b), "l"(c));
    return d;
}

// ---------------------------------------------------------------------------
// Kernel 1: per-row squared norms + p = x@(W1a-W1b)+b1, q = x@W1b
// ---------------------------------------------------------------------------
__global__ __launch_bounds__(256) void pq_kernel(const float* __restrict__ x,
                                                 const float* __restrict__ W1,
                                                 const float* __restrict__ b1) {
    __shared__ float sx[8 * D];
    const int i0 = blockIdx.x * 8;
    const int t = threadIdx.x;

    for (int u = t; u < 8 * D; u += 256) sx[u] = x[i0 * D + u];
    __syncthreads();

    if (t < 8) {
        float s = 0.f;
        #pragma unroll
        for (int d = 0; d < D; d++) { float v = sx[t * D + d]; s = fmaf(v, v, s); }
        g_sq[i0 + t] = s;
    }

    float acc[8];
    #pragma unroll
    for (int m = 0; m < 8; m++) acc[m] = 0.f;

    if (t < DO) {
        const int c = t;
        for (int d = 0; d < D; d++) {
            float w = W1[d * DO + c] - W1[(D + d) * DO + c];
            #pragma unroll
            for (int m = 0; m < 8; m++) acc[m] = fmaf(sx[m * D + d], w, acc[m]);
        }
        float bb = b1[c];
        #pragma unroll
        for (int m = 0; m < 8; m++) g_p[(size_t)(i0 + m) * DO + c] = acc[m] + bb;
    } else {
        const int c = t - DO;
        for (int d = 0; d < D; d++) {
            float w = W1[(D + d) * DO + c];
            #pragma unroll
            for (int m = 0; m < 8; m++) acc[m] = fmaf(sx[m * D + d], w, acc[m]);
        }
        #pragma unroll
        for (int m = 0; m < 8; m++) g_q[(size_t)(i0 + m) * DO + c] = acc[m];
    }
}

// ---------------------------------------------------------------------------
// Kernel 2: kNN as register-tiled FFMA2 GEMM (i-pairs) + fused top-16 scan.
// grid = (NN/TI, SEG), block = 128 threads (16 ty-groups x 8 tx).
// smem: a[d][ip] (i-pairs), b[d][j] (value duplicated into both b64 halves),
// dist[j][i] raw dot products. 101.9KB dynamic -> 2 CTAs/SM.
// ---------------------------------------------------------------------------
struct KnnSmem {
    u64 a[64][66];        // [d][ip] pairs (x[2ip][d], x[2ip+1][d])  33792B
    u64 b[64][66];        // [d][j] dup (v,v)                        33792B
    float dist[TJ][132];  // [j][i] raw dot                          33792B
    float sqj[2][TJ];     //                                           512B
};
#define KNN_SMEM_BYTES sizeof(KnnSmem)

__global__ __launch_bounds__(128, 2) void knn_kernel(const float* __restrict__ x) {
    extern __shared__ char smraw[];
    KnnSmem& sm = *reinterpret_cast<KnnSmem*>(smraw);
    const int t = threadIdx.x;
    const int tx = t & 7;      // j lane: j = tx + 8m
    const int ty = t >> 3;     // i group: i = ty*8 + ...
    const int ib = blockIdx.x * TI;
    const int s = blockIdx.y;

    const float4* x4 = reinterpret_cast<const float4*>(x);

    // ---- Prologue: stage A (i-pairs), B(0) (dup), sqj[0]; load own si. ----
    {
        // A: thread t owns row ib+t; scatter into a[d][t>>1] halves.
        float4 v[16];
        #pragma unroll
        for (int q = 0; q < 16; q++) v[q] = x4[(size_t)(ib + t) * 16 + q];
        float* dsta = reinterpret_cast<float*>(&sm.a[0][0]) + (t >> 1) * 2 + (t & 1);
        #pragma unroll
        for (int q = 0; q < 16; q++) {
            dsta[(q * 4 + 0) * 132] = v[q].x;
            dsta[(q * 4 + 1) * 132] = v[q].y;
            dsta[(q * 4 + 2) * 132] = v[q].z;
            dsta[(q * 4 + 3) * 132] = v[q].w;
        }
        // B(0): thread handles j = t&63, d-half = t>>6.
        const int j = t & 63, dh = t >> 6;
        const int jb0 = s * JSEG;
        #pragma unroll
        for (int q = 0; q < 8; q++) {
            float4 w = x4[(size_t)(jb0 + j) * 16 + dh * 8 + q];
            int d0 = dh * 32 + q * 4;
            float fv[4] = {w.x, w.y, w.z, w.w};
            #pragma unroll
            for (int e = 0; e < 4; e++) {
                unsigned r = __float_as_uint(fv[e]);
                asm volatile("st.shared.v2.b32 [%0], {%1,%1};"
                             :: "l"(&sm.b[d0 + e][j]), "r"(r) : "memory");
            }
        }
        if (t < TJ) sm.sqj[0][t] = g_sq[jb0 + t];
    }
    const float si = g_sq[ib + t];
    __syncthreads();

    float kd[K];
    int   kj[K];
    #pragma unroll
    for (int n = 0; n < K; n++) { kd[n] = 3.4e38f; kj[n] = 0; }

    for (int tt = 0; tt < NTILES; tt++) {
        // Prefetch next B tile into registers (hidden under GEMM).
        float4 pv[8];
        float psq = 0.f;
        if (tt + 1 < NTILES) {
            const int j = t & 63, dh = t >> 6;
            const int jbn = s * JSEG + (tt + 1) * TJ;
            #pragma unroll
            for (int q = 0; q < 8; q++)
                pv[q] = x4[(size_t)(jbn + j) * 16 + dh * 8 + q];
            if (t < TJ) psq = g_sq[jbn + t];
        }

        // ---- GEMM: acc[p][m] = pair-dot over d. ----
        u64 acc[4][8];
        #pragma unroll
        for (int p = 0; p < 4; p++)
            #pragma unroll
            for (int m = 0; m < 8; m++) acc[p][m] = 0ull;

        #pragma unroll 8
        for (int d = 0; d < 64; d++) {
            const u64* ar = &sm.a[d][ty * 4];
            ulonglong2 apA = *reinterpret_cast<const ulonglong2*>(ar);
            ulonglong2 apB = *reinterpret_cast<const ulonglong2*>(ar + 2);
            u64 ap[4] = {apA.x, apA.y, apB.x, apB.y};
            u64 bv[8];
            #pragma unroll
            for (int m = 0; m < 8; m++) bv[m] = sm.b[d][tx + 8 * m];
            #pragma unroll
            for (int p = 0; p < 4; p++)
                #pragma unroll
                for (int m = 0; m < 8; m++)
                    acc[p][m] = ffma2(ap[p], bv[m], acc[p][m]);
        }
        __syncthreads();   // all warps done reading b

        // ---- Store prefetched B(t+1) + sqj. ----
        if (tt + 1 < NTILES) {
            const int j = t & 63, dh = t >> 6;
            #pragma unroll
            for (int q = 0; q < 8; q++) {
                int d0 = dh * 32 + q * 4;
                float fv[4] = {pv[q].x, pv[q].y, pv[q].z, pv[q].w};
                #pragma unroll
                for (int e = 0; e < 4; e++) {
                    unsigned r = __float_as_uint(fv[e]);
                    asm volatile("st.shared.v2.b32 [%0], {%1,%1};"
                                 :: "l"(&sm.b[d0 + e][j]), "r"(r) : "memory");
                }
            }
            if (t < TJ) sm.sqj[(tt + 1) & 1][t] = psq;
        }

        // ---- Epilogue: raw dots -> dist[j][i] (STS.64 pairs). ----
        #pragma unroll
        for (int p = 0; p < 4; p++) {
            const int i0 = ty * 8 + 2 * p;
            #pragma unroll
            for (int m = 0; m < 8; m++) {
                const int j = tx + 8 * m;
                *reinterpret_cast<u64*>(&sm.dist[j][i0]) = acc[p][m];
            }
        }
        __syncthreads();   // dist(t) and b(t+1) ready

        // ---- Scan: thread t owns i-row t; fp32 semantics match R2. ----
        const int jb = s * JSEG + tt * TJ;
        const float* sqjp = sm.sqj[tt & 1];
        #pragma unroll 4
        for (int jj = 0; jj < TJ; jj++) {
            float dot = sm.dist[jj][t];
            float dv = fmaf(-2.f, dot, si + sqjp[jj]);
            if (dv < kd[K - 1]) {
                kd[K - 1] = dv; kj[K - 1] = jb + jj;
                #pragma unroll
                for (int n = K - 1; n > 0; n--) {
                    if (kd[n] < kd[n - 1]) {
                        float td = kd[n]; kd[n] = kd[n - 1]; kd[n - 1] = td;
                        int   tj = kj[n]; kj[n] = kj[n - 1]; kj[n - 1] = tj;
                    }
                }
            }
        }
    }

    // Writeout: total-order u64 keys, ascending.
    u64* dst = g_ck + ((size_t)(ib + t) * SEG + s) * K;
    #pragma unroll
    for (int n = 0; n < K; n++) {
        unsigned u = __float_as_uint(kd[n]);
        u = (u & 0x80000000u) ? ~u : (u | 0x80000000u);
        dst[n] = ((u64)u << 32) | (unsigned)kj[n];
    }
}

// ---------------------------------------------------------------------------
// Kernel 3: merge SEG x 16 candidates per row, aggregate, apply W2.
// ---------------------------------------------------------------------------
__global__ __launch_bounds__(128) void agg_kernel(const float* __restrict__ W2,
                                                  const float* __restrict__ b2,
                                                  float* __restrict__ out) {
    __shared__ u64 skey[SEG * K];
    __shared__ int snbr[K];
    __shared__ float sr[DO];
    const int i = blockIdx.x;
    const int t = threadIdx.x;

    skey[t] = g_ck[(size_t)i * SEG * K + t];
    __syncthreads();
    {
        u64 mk = skey[t];
        int rank = 0;
        #pragma unroll 4
        for (int u = 0; u < SEG * K; u++) rank += (skey[u] < mk);
        if (rank < K) snbr[rank] = (int)(mk & 0xFFFFFFFFull);
    }
    __syncthreads();

    float p = g_p[(size_t)i * DO + t];
    float acc = 0.f;
    #pragma unroll
    for (int n = 0; n < K; n++) {
        int j = snbr[n];
        acc += fmaxf(p + g_q[(size_t)j * DO + t], 0.f);
    }
    sr[t] = acc * (1.f / K);
    __syncthreads();

    float o = b2[t];
    #pragma unroll 8
    for (int d = 0; d < DO; d++)
        o = fmaf(sr[d], W2[d * DO + t], o);
    out[(size_t)i * DO + t] = o;
}

// ---------------------------------------------------------------------------
extern "C" void kernel_launch(void* const* d_in, const int* in_sizes, int n_in,
                              void* d_out, int out_size) {
    const float* x  = (const float*)d_in[0];
    const float* W1 = (const float*)d_in[1];
    const float* b1 = (const float*)d_in[2];
    const float* W2 = (const float*)d_in[3];
    const float* b2 = (const float*)d_in[4];
    float* out = (float*)d_out;

    cudaFuncSetAttribute(knn_kernel, cudaFuncAttributeMaxDynamicSharedMemorySize,
                         (int)KNN_SMEM_BYTES);

    pq_kernel<<<NN / 8, 256>>>(x, W1, b1);
    knn_kernel<<<dim3(NN / TI, SEG), 128, KNN_SMEM_BYTES>>>(x);
    agg_kernel<<<NN, 128>>>(W2, b2, out);
}

// round 7
// speedup vs baseline: 1.2854x; 1.2854x over previous
#include <cuda_runtime.h>
#include <cstdint>

#define NN 8192
#define D 64
#define DO 128
#define K 16
#define SEG 8
#define JSEG (NN/SEG)
#define TJ 32

typedef unsigned long long u64;

// Scratch (no allocs allowed in kernel_launch)
__device__ float g_sq[NN];
__device__ float g_p[NN * DO];
__device__ float g_q[NN * DO];
__device__ u64 g_ck[NN * SEG * K];

// Packed fp32x2 math (Blackwell FFMA2 path — only reachable via PTX)
__device__ __forceinline__ u64 ffma2(u64 a, u64 b, u64 c) {
    u64 d;
    asm("fma.rn.f32x2 %0, %1, %2, %3;" : "=l"(d) : "l"(a), "l"(b), "l"(c));
    return d;
}
__device__ __forceinline__ u64 fadd2(u64 a, u64 b) {
    u64 d;
    asm("add.rn.f32x2 %0, %1, %2;" : "=l"(d) : "l"(a), "l"(b));
    return d;
}

// ---------------------------------------------------------------------------
// Kernel 1: per-row squared norms + p = x@(W1a-W1b)+b1, q = x@W1b
// ---------------------------------------------------------------------------
__global__ __launch_bounds__(256) void pq_kernel(const float* __restrict__ x,
                                                 const float* __restrict__ W1,
                                                 const float* __restrict__ b1) {
    __shared__ float sx[8 * D];
    const int i0 = blockIdx.x * 8;
    const int t = threadIdx.x;

    for (int u = t; u < 8 * D; u += 256) sx[u] = x[i0 * D + u];
    __syncthreads();

    if (t < 8) {
        float s = 0.f;
        #pragma unroll
        for (int d = 0; d < D; d++) { float v = sx[t * D + d]; s = fmaf(v, v, s); }
        g_sq[i0 + t] = s;
    }

    float acc[8];
    #pragma unroll
    for (int m = 0; m < 8; m++) acc[m] = 0.f;

    if (t < DO) {
        const int c = t;
        for (int d = 0; d < D; d++) {
            float w = W1[d * DO + c] - W1[(D + d) * DO + c];
            #pragma unroll
            for (int m = 0; m < 8; m++) acc[m] = fmaf(sx[m * D + d], w, acc[m]);
        }
        float bb = b1[c];
        #pragma unroll
        for (int m = 0; m < 8; m++) g_p[(size_t)(i0 + m) * DO + c] = acc[m] + bb;
    } else {
        const int c = t - DO;
        for (int d = 0; d < D; d++) {
            float w = W1[(D + d) * DO + c];
            #pragma unroll
            for (int m = 0; m < 8; m++) acc[m] = fmaf(sx[m * D + d], w, acc[m]);
        }
        #pragma unroll
        for (int m = 0; m < 8; m++) g_q[(size_t)(i0 + m) * DO + c] = acc[m];
    }
}

// ---------------------------------------------------------------------------
// Kernel 2: kNN, R2 broadcast-scan structure + deferred candidate buffer.
// grid = (N/128, SEG). Thread owns query row i; hot loop is branch-free
// (predicated append to a private smem column); drain per 32-j tile with
// early-exit sorted insert into register top-16.
// ---------------------------------------------------------------------------
struct KnnSmem {
    ulonglong2 sj[TJ * 16];   // 32 rows x 256B verbatim          8192B
    float ssq[TJ];            //                                    128B
    u64 cand[TJ + 1][128];    // [slot][thread], row TJ = dummy  33792B
};
#define KNN_SMEM_BYTES sizeof(KnnSmem)

__global__ __launch_bounds__(128, 4) void knn_kernel(const float* __restrict__ x) {
    extern __shared__ char smraw[];
    KnnSmem& sm = *reinterpret_cast<KnnSmem*>(smraw);
    const int tid = threadIdx.x;
    const int i = blockIdx.x * 128 + tid;
    const int s = blockIdx.y;

    // Query row packed as 16x ulonglong2 (32 f32x2 pairs) in registers.
    ulonglong2 xi[16];
    const ulonglong2* xr = reinterpret_cast<const ulonglong2*>(x) + (size_t)i * 16;
    #pragma unroll
    for (int c = 0; c < 16; c++) xi[c] = xr[c];
    const float sqi = g_sq[i];

    float kd[K];
    int   kj[K];
    #pragma unroll
    for (int n = 0; n < K; n++) { kd[n] = 3.4e38f; kj[n] = 0; }
    float thresh = 3.4e38f;
    int cnt = 0;

    const int jbeg = s * JSEG, jend = jbeg + JSEG;
    for (int jb = jbeg; jb < jend; jb += TJ) {
        const ulonglong2* gs = reinterpret_cast<const ulonglong2*>(x) + (size_t)jb * 16;
        #pragma unroll
        for (int u = tid; u < TJ * 16; u += 128) sm.sj[u] = gs[u];
        if (tid < TJ) sm.ssq[tid] = g_sq[jb + tid];
        __syncthreads();

        // ---- Hot loop: branch-free scan + predicated append ----
        #pragma unroll 2
        for (int jj = 0; jj < TJ; jj++) {
            u64 a0 = 0ull, a1 = 0ull, a2 = 0ull, a3 = 0ull;
            #pragma unroll
            for (int c = 0; c < 16; c += 2) {
                ulonglong2 v0 = sm.sj[jj * 16 + c];
                ulonglong2 v1 = sm.sj[jj * 16 + c + 1];
                a0 = ffma2(xi[c].x, v0.x, a0);
                a1 = ffma2(xi[c].y, v0.y, a1);
                a2 = ffma2(xi[c + 1].x, v1.x, a2);
                a3 = ffma2(xi[c + 1].y, v1.y, a3);
            }
            u64 st = fadd2(fadd2(a0, a1), fadd2(a2, a3));
            unsigned lo, hi;
            asm("mov.b64 {%0, %1}, %2;" : "=r"(lo), "=r"(hi) : "l"(st));
            float dot = __uint_as_float(lo) + __uint_as_float(hi);
            float dist = fmaf(-2.f, dot, sqi + sm.ssq[jj]);

            int flag = (dist < thresh) ? 1 : 0;
            int row = flag ? cnt : TJ;          // row TJ = dummy sink
            sm.cand[row][tid] =
                ((u64)__float_as_uint(dist) << 32) | (unsigned)(jb + jj);
            cnt += flag;
        }

        // ---- Drain private buffer (cold path) ----
        for (int c = 0; c < cnt; c++) {
            u64 e = sm.cand[c][tid];
            float dv = __uint_as_float((unsigned)(e >> 32));
            int jv = (int)(e & 0xFFFFFFFFull);
            if (dv < kd[K - 1]) {
                kd[K - 1] = dv; kj[K - 1] = jv;
                #pragma unroll
                for (int n = K - 1; n > 0; n--) {
                    if (kd[n] < kd[n - 1]) {
                        float td = kd[n]; kd[n] = kd[n - 1]; kd[n - 1] = td;
                        int   tj = kj[n]; kj[n] = kj[n - 1]; kj[n - 1] = tj;
                    } else break;
                }
            }
        }
        cnt = 0;
        thresh = kd[K - 1];
        __syncthreads();
    }

    // Writeout: total-order u64 keys, ascending.
    u64* dst = g_ck + ((size_t)i * SEG + s) * K;
    #pragma unroll
    for (int n = 0; n < K; n++) {
        unsigned u = __float_as_uint(kd[n]);
        u = (u & 0x80000000u) ? ~u : (u | 0x80000000u);  // total order
        dst[n] = ((u64)u << 32) | (unsigned)kj[n];
    }
}

// ---------------------------------------------------------------------------
// Kernel 3: merge SEG x 16 candidates per row, aggregate, apply W2.
// ---------------------------------------------------------------------------
__global__ __launch_bounds__(128) void agg_kernel(const float* __restrict__ W2,
                                                  const float* __restrict__ b2,
                                                  float* __restrict__ out) {
    __shared__ u64 skey[SEG * K];
    __shared__ int snbr[K];
    __shared__ float sr[DO];
    const int i = blockIdx.x;
    const int t = threadIdx.x;

    skey[t] = g_ck[(size_t)i * SEG * K + t];
    __syncthreads();
    {
        u64 mk = skey[t];
        int rank = 0;
        #pragma unroll 4
        for (int u = 0; u < SEG * K; u++) rank += (skey[u] < mk);
        if (rank < K) snbr[rank] = (int)(mk & 0xFFFFFFFFull);
    }
    __syncthreads();

    float p = g_p[(size_t)i * DO + t];
    float acc = 0.f;
    #pragma unroll
    for (int n = 0; n < K; n++) {
        int j = snbr[n];
        acc += fmaxf(p + g_q[(size_t)j * DO + t], 0.f);
    }
    sr[t] = acc * (1.f / K);
    __syncthreads();

    float o = b2[t];
    #pragma unroll 8
    for (int d = 0; d < DO; d++)
        o = fmaf(sr[d], W2[d * DO + t], o);
    out[(size_t)i * DO + t] = o;
}

// ---------------------------------------------------------------------------
extern "C" void kernel_launch(void* const* d_in, const int* in_sizes, int n_in,
                              void* d_out, int out_size) {
    const float* x  = (const float*)d_in[0];
    const float* W1 = (const float*)d_in[1];
    const float* b1 = (const float*)d_in[2];
    const float* W2 = (const float*)d_in[3];
    const float* b2 = (const float*)d_in[4];
    float* out = (float*)d_out;

    cudaFuncSetAttribute(knn_kernel, cudaFuncAttributeMaxDynamicSharedMemorySize,
                         (int)KNN_SMEM_BYTES);

    pq_kernel<<<NN / 8, 256>>>(x, W1, b1);
    knn_kernel<<<dim3(NN / 128, SEG), 128, KNN_SMEM_BYTES>>>(x);
    agg_kernel<<<NN, 128>>>(W2, b2, out);
}